// round 6
// baseline (speedup 1.0000x reference)
#include <cuda_runtime.h>
#include <math.h>

#define Bc   32
#define CHc  32
#define Hc   128
#define Wcn  128
#define M1c  16
#define M2c  16
#define NLc  4
#define Ec   8
#define HDc  64
#define NHc  4
#define NENCc 2
#define PCHc 128
#define Sc   128

// ---------------- scratch (device globals; no dynamic allocation) -------------
__device__ float  g_v [Bc*CHc*Hc*Wcn];          // 64 MB
__device__ float  g_v2[Bc*CHc*Hc*Wcn];          // 64 MB
__device__ float2 g_Xw[Bc*CHc*Hc*M2c];          // 16 MB  (DFT along w)
__device__ float2 g_Xm[Bc*CHc*2*M1c*M2c];       // 4 MB   (modes)
__device__ float2 g_Om[Bc*CHc*2*M1c*M2c];       // 4 MB   (after spectral mult)
__device__ float2 g_Yh[Bc*CHc*Hc*M2c];          // 16 MB  (after inverse DFT along h)
__device__ int    g_idx[Bc];
__device__ float2 g_tw[128];                    // (cos, sin)(2*pi*t/128)
// router scratch
__device__ float g_rh[Bc*Sc*HDc];
__device__ float g_rq[Bc*Sc*192];
__device__ float g_ro[Bc*Sc*HDc];
__device__ float g_rt[Bc*Sc*HDc];
__device__ float g_ra[Bc*Sc*256];

__device__ __forceinline__ float gelu_f(float x) {
    float x3 = x*x*x;
    return 0.5f*x*(1.0f + tanhf(0.7978845608028654f*(x + 0.044715f*x3)));
}

// ---------------- twiddle init ------------------------------------------------
__global__ void init_tw_kernel() {
    int t = threadIdx.x;
    if (t < 128) g_tw[t] = make_float2(cospif(t/64.0f), sinpif(t/64.0f));
}

// ---------------- router ------------------------------------------------------
__device__ void ln_rows(const float* tin, float* hout,
                        const float* sca, const float* bia, int tid) {
    int warp = tid >> 5, lane = tid & 31;
    for (int r = warp; r < Sc; r += 8) {
        const float* row = tin + r*HDc;
        float a0 = row[lane], a1 = row[lane+32];
        float sum = a0 + a1;
        #pragma unroll
        for (int off = 16; off; off >>= 1) sum += __shfl_xor_sync(0xffffffffu, sum, off);
        float mu = sum * (1.0f/64.0f);
        float d0 = a0 - mu, d1 = a1 - mu;
        float vs = d0*d0 + d1*d1;
        #pragma unroll
        for (int off = 16; off; off >>= 1) vs += __shfl_xor_sync(0xffffffffu, vs, off);
        float inv = rsqrtf(vs*(1.0f/64.0f) + 1e-5f);
        hout[r*HDc + lane]      = d0*inv*sca[lane]      + bia[lane];
        hout[r*HDc + lane + 32] = d1*inv*sca[lane+32]   + bia[lane+32];
    }
}

__global__ void router_kernel(
    const float* __restrict__ x,
    const float* __restrict__ enc_in_w, const float* __restrict__ enc_in_b,
    const float* __restrict__ qkv_w,    const float* __restrict__ qkv_b,
    const float* __restrict__ ao_w,     const float* __restrict__ ao_b,
    const float* __restrict__ ln1_s,    const float* __restrict__ ln1_b,
    const float* __restrict__ ff1_w,    const float* __restrict__ ff1_b,
    const float* __restrict__ ff2_w,    const float* __restrict__ ff2_b,
    const float* __restrict__ ln2_s,    const float* __restrict__ ln2_b,
    const float* __restrict__ fc_w,     const float* __restrict__ fc_b)
{
    int b = blockIdx.x;
    int tid = threadIdx.x;               // 256 threads
    float* h  = g_rh + b*Sc*HDc;
    float* qk = g_rq + b*Sc*192;
    float* o  = g_ro + b*Sc*HDc;
    float* tb = g_rt + b*Sc*HDc;
    float* ac = g_ra + b*Sc*256;
    const float* xb = x + (long)b*Hc*Wcn;   // x[b,0,0,:] = first W of the image

    // h = ic @ enc_in_w + enc_in_b   (CIN=1)
    for (int i = tid; i < Sc*HDc; i += 256) {
        int s = i >> 6, d = i & 63;
        h[i] = xb[s]*enc_in_w[d] + enc_in_b[d];
    }
    __syncthreads();

    for (int l = 0; l < NENCc; l++) {
        // qkv = h @ qkv_w[l] + qkv_b[l]
        const float* qw = qkv_w + l*HDc*192;
        for (int i = tid; i < Sc*192; i += 256) {
            int s = i/192, j = i - s*192;
            float acc = qkv_b[l*192 + j];
            const float* hr = h + s*HDc;
            for (int d = 0; d < HDc; d++) acc += hr[d]*qw[d*192 + j];
            qk[i] = acc;
        }
        __syncthreads();

        // attention: one warp per (q, head)
        {
            int warp = tid >> 5, lane = tid & 31;
            for (int it = warp; it < Sc*NHc; it += 8) {
                int q = it >> 2, hh = it & 3;
                const float* qrow = qk + q*192 + hh*16;
                float qv[16];
                #pragma unroll
                for (int dd = 0; dd < 16; dd++) qv[dd] = qrow[dd];
                float sc[4];
                #pragma unroll
                for (int j = 0; j < 4; j++) {
                    int k = lane + 32*j;
                    const float* krow = qk + k*192 + 64 + hh*16;
                    float s = 0.f;
                    #pragma unroll
                    for (int dd = 0; dd < 16; dd++) s += qv[dd]*krow[dd];
                    sc[j] = s*0.25f;                 // 1/sqrt(16)
                }
                float m = fmaxf(fmaxf(sc[0],sc[1]), fmaxf(sc[2],sc[3]));
                #pragma unroll
                for (int off = 16; off; off >>= 1) m = fmaxf(m, __shfl_xor_sync(0xffffffffu, m, off));
                float e[4], ssum = 0.f;
                #pragma unroll
                for (int j = 0; j < 4; j++) { e[j] = expf(sc[j] - m); ssum += e[j]; }
                #pragma unroll
                for (int off = 16; off; off >>= 1) ssum += __shfl_xor_sync(0xffffffffu, ssum, off);
                float accv[16];
                #pragma unroll
                for (int dd = 0; dd < 16; dd++) accv[dd] = 0.f;
                #pragma unroll
                for (int j = 0; j < 4; j++) {
                    int k = lane + 32*j;
                    const float* vrow = qk + k*192 + 128 + hh*16;
                    #pragma unroll
                    for (int dd = 0; dd < 16; dd++) accv[dd] += e[j]*vrow[dd];
                }
                #pragma unroll
                for (int dd = 0; dd < 16; dd++) {
                    #pragma unroll
                    for (int off = 16; off; off >>= 1)
                        accv[dd] += __shfl_xor_sync(0xffffffffu, accv[dd], off);
                }
                if (lane == 0) {
                    float inv = 1.0f/ssum;
                    #pragma unroll
                    for (int dd = 0; dd < 16; dd++) o[q*HDc + hh*16 + dd] = accv[dd]*inv;
                }
            }
        }
        __syncthreads();

        // t = h + o @ ao_w[l] + ao_b[l]; LN1 -> h
        const float* aw = ao_w + l*HDc*HDc;
        for (int i = tid; i < Sc*HDc; i += 256) {
            int s = i >> 6, d = i & 63;
            float acc = h[i] + ao_b[l*HDc + d];
            const float* orow = o + s*HDc;
            for (int e2 = 0; e2 < HDc; e2++) acc += orow[e2]*aw[e2*HDc + d];
            tb[i] = acc;
        }
        __syncthreads();
        ln_rows(tb, h, ln1_s + l*HDc, ln1_b + l*HDc, tid);
        __syncthreads();

        // ff
        const float* f1 = ff1_w + l*HDc*256;
        for (int i = tid; i < Sc*256; i += 256) {
            int s = i >> 8, e2 = i & 255;
            float acc = ff1_b[l*256 + e2];
            const float* hr = h + s*HDc;
            for (int d = 0; d < HDc; d++) acc += hr[d]*f1[d*256 + e2];
            ac[i] = fmaxf(acc, 0.0f);
        }
        __syncthreads();
        const float* f2 = ff2_w + l*256*HDc;
        for (int i = tid; i < Sc*HDc; i += 256) {
            int s = i >> 6, d = i & 63;
            float acc = h[i] + ff2_b[l*HDc + d];
            const float* ar = ac + s*256;
            for (int e2 = 0; e2 < 256; e2++) acc += ar[e2]*f2[e2*HDc + d];
            tb[i] = acc;
        }
        __syncthreads();
        ln_rows(tb, h, ln2_s + l*HDc, ln2_b + l*HDc, tid);
        __syncthreads();
    }

    // feats = mean_s h; logits = feats@fc_w + fc_b; argmax (first max)
    __shared__ float feats[HDc];
    for (int d = tid; d < HDc; d += 256) {
        float s = 0.f;
        for (int q = 0; q < Sc; q++) s += h[q*HDc + d];
        feats[d] = s * (1.0f/Sc);
    }
    __syncthreads();
    if (tid == 0) {
        float best = -3.4e38f; int bi = 0;
        for (int c = 0; c < Ec; c++) {
            float acc = fc_b[c];
            for (int d = 0; d < HDc; d++) acc += feats[d]*fc_w[d*Ec + c];
            if (acc > best) { best = acc; bi = c; }
        }
        g_idx[b] = bi;
    }
}

// ---------------- FNO: lift ---------------------------------------------------
__global__ void lift_kernel(const float* __restrict__ x,
                            const float* __restrict__ lift_w,
                            const float* __restrict__ lift_b)
{
    int p  = blockIdx.x*256 + threadIdx.x;   // [0, B*H*W)
    int b  = p >> 14;
    int hw = p & 16383;
    __shared__ float lw[CHc], lb[CHc];
    if (threadIdx.x < CHc) {
        int e = g_idx[b];                    // whole block maps to one b (64 blocks / b)
        lw[threadIdx.x] = lift_w[e*CHc + threadIdx.x];
        lb[threadIdx.x] = lift_b[e*CHc + threadIdx.x];
    }
    __syncthreads();
    float xv = x[p];
    float* vb = g_v + (long)b*CHc*Hc*Wcn + hw;
    #pragma unroll
    for (int d = 0; d < CHc; d++) vb[(long)d*Hc*Wcn] = xv*lw[d] + lb[d];
}

// ---------------- F1: partial DFT along w (128 real -> 16 complex) ------------
__global__ void dftw_kernel(int l)
{
    const float* vin = (l & 1) ? g_v2 : g_v;
    __shared__ float sv[8][129];
    __shared__ float twc[128], tws[128];
    int tid = threadIdx.x;                   // 128
    { float2 t = g_tw[tid]; twc[tid] = t.x; tws[tid] = t.y; }
    long base = (long)blockIdx.x * 1024;     // 8 rows of 128
    #pragma unroll
    for (int i = tid; i < 1024; i += 128) sv[i>>7][i&127] = vin[base + i];
    __syncthreads();
    int r = tid >> 4, ky = tid & 15;
    float re = 0.f, im = 0.f;
    #pragma unroll 4
    for (int w = 0; w < 128; w++) {
        int t = (ky*w) & 127;
        float v = sv[r][w];
        re += v*twc[t];
        im -= v*tws[t];
    }
    g_Xw[blockIdx.x*128 + r*16 + ky] = make_float2(re, im);
}

// ---------------- F2: DFT along h at 32 kept kx -------------------------------
__global__ void dfth_kernel()
{
    __shared__ float2 sx[2048];              // [h][ky]
    __shared__ float twc[128], tws[128];
    int tid = threadIdx.x;                   // 512
    if (tid < 128) { float2 t = g_tw[tid]; twc[tid] = t.x; tws[tid] = t.y; }
    long base = (long)blockIdx.x * 2048;     // blockIdx = b*CH + i
    #pragma unroll
    for (int i = tid; i < 2048; i += 512) sx[i] = g_Xw[base + i];
    __syncthreads();
    int j = tid >> 4, ky = tid & 15;
    int kx = (j < 16) ? j : j + 96;          // 112..127 = -16..-1 block
    float re = 0.f, im = 0.f;
    #pragma unroll 4
    for (int hh = 0; hh < 128; hh++) {
        float2 c = sx[hh*16 + ky];
        int t = (kx*hh) & 127;
        float cc = twc[t], ss = tws[t];      // e^{-i th}
        re += c.x*cc + c.y*ss;
        im += c.y*cc - c.x*ss;
    }
    g_Xm[blockIdx.x*512 + j*16 + ky] = make_float2(re, im);
}

// ---------------- F3: per-mode CH x CH complex contraction --------------------
__global__ void spec_kernel(const float* __restrict__ wr,
                            const float* __restrict__ wi, int l)
{
    __shared__ float2 sX[512];               // [i][ky]
    int tid = threadIdx.x;                   // 512
    int b = blockIdx.x >> 5;
    int j = blockIdx.x & 31;
    int e = g_idx[b];
    {
        int i = tid >> 4, ky = tid & 15;
        sX[tid] = g_Xm[(b*CHc + i)*512 + j*16 + ky];
    }
    __syncthreads();
    int o = tid >> 4, ky = tid & 15;
    int blk = (j < 16) ? 0 : 1;
    int m1  = j & 15;
    long wbase = ((long)((e*NLc + l)*2 + blk)*CHc*CHc)*256 + (long)o*256 + m1*16 + ky;
    float re = 0.f, im = 0.f;
    #pragma unroll 8
    for (int i = 0; i < CHc; i++) {
        float2 X = sX[i*16 + ky];
        float a = wr[wbase + (long)i*CHc*256];
        float c = wi[wbase + (long)i*CHc*256];
        re += X.x*a - X.y*c;
        im += X.x*c + X.y*a;
    }
    g_Om[(b*CHc + o)*512 + j*16 + ky] = make_float2(re, im);
}

// ---------------- F4: inverse DFT along h (32 kx -> 128 h) --------------------
__global__ void idfth_kernel()
{
    __shared__ float2 sO[512];               // [j][ky]
    __shared__ float twc[128], tws[128];
    int tid = threadIdx.x;                   // 512
    if (tid < 128) { float2 t = g_tw[tid]; twc[tid] = t.x; tws[tid] = t.y; }
    long base = (long)blockIdx.x * 512;      // blockIdx = b*CH + o
    sO[tid] = g_Om[base + tid];
    __syncthreads();
    int ky = tid & 15;
    int hh = tid >> 4;                       // 0..31
    for (int m = 0; m < 4; m++) {
        int h = hh + 32*m;
        float re = 0.f, im = 0.f;
        #pragma unroll
        for (int j = 0; j < 32; j++) {
            int kx = (j < 16) ? j : j + 96;
            float2 c = sO[j*16 + ky];
            int t = (kx*h) & 127;
            float cc = twc[t], ss = tws[t];  // e^{+i th}
            re += c.x*cc - c.y*ss;
            im += c.x*ss + c.y*cc;
        }
        g_Yh[((long)blockIdx.x*128 + h)*16 + ky] = make_float2(re, im);
    }
}

// -------- F5: real inverse DFT along w + skip conv + (gelu) -------------------
__global__ void combine_kernel(const float* __restrict__ skip_w,
                               const float* __restrict__ skip_b, int l)
{
    const float* vin  = (l & 1) ? g_v2 : g_v;
    float*       vout = (l & 1) ? g_v  : g_v2;
    __shared__ float  sv[CHc][129];
    __shared__ float2 sy[CHc*16];
    __shared__ float  sw[CHc*CHc];
    __shared__ float  sb[CHc];
    __shared__ float  twc[128], tws[128];
    int tid = threadIdx.x;                   // 128
    int b = blockIdx.x >> 7;
    int h = blockIdx.x & 127;
    int e = g_idx[b];
    { float2 t = g_tw[tid]; twc[tid] = t.x; tws[tid] = t.y; }
    #pragma unroll
    for (int i = 0; i < CHc; i++)
        sv[i][tid] = vin[(((long)(b*CHc + i))*Hc + h)*Wcn + tid];
    for (int i = tid; i < CHc*16; i += 128)
        sy[i] = g_Yh[((long)(b*CHc + (i>>4)))*Hc*16 + h*16 + (i & 15)];
    for (int i = tid; i < CHc*CHc; i += 128)
        sw[i] = skip_w[((long)(e*NLc + l))*CHc*CHc + i];
    if (tid < CHc) sb[tid] = skip_b[(e*NLc + l)*CHc + tid];
    __syncthreads();

    int w = tid;
    const float scale = 1.0f/(Hc*Wcn);
    int do_act = (l < NLc - 1);
    for (int o = 0; o < CHc; o++) {
        // irfft along w: DC (real part only) + 2*Re(sum_{ky>=1} Y e^{+i th})
        float s = sy[o*16].x;
        #pragma unroll
        for (int ky = 1; ky < 16; ky++) {
            int t = (ky*w) & 127;
            float2 c = sy[o*16 + ky];
            s += 2.0f*(c.x*twc[t] - c.y*tws[t]);
        }
        s *= scale;
        float sk = sb[o];
        #pragma unroll 8
        for (int i = 0; i < CHc; i++) sk += sv[i][w]*sw[i*CHc + o];
        float r = s + sk;
        if (do_act) r = gelu_f(r);
        vout[(((long)(b*CHc + o))*Hc + h)*Wcn + w] = r;
    }
}

// ---------------- fused p1 (gelu) + p2 projection -----------------------------
__global__ void proj_kernel(float* __restrict__ out,
                            const float* __restrict__ p1_w, const float* __restrict__ p1_b,
                            const float* __restrict__ p2_w, const float* __restrict__ p2_b)
{
    const float* vin = g_v;                  // after 4 layers, final v lives in g_v
    __shared__ float sv[CHc][129];
    __shared__ float sp1[CHc*PCHc];
    __shared__ float sp1b[PCHc], sp2[PCHc];
    int tid = threadIdx.x;                   // 128
    int b = blockIdx.x >> 7;
    int h = blockIdx.x & 127;
    int e = g_idx[b];
    #pragma unroll
    for (int i = 0; i < CHc; i++)
        sv[i][tid] = vin[(((long)(b*CHc + i))*Hc + h)*Wcn + tid];
    for (int i = tid; i < CHc*PCHc; i += 128) sp1[i] = p1_w[(long)e*CHc*PCHc + i];
    sp1b[tid] = p1_b[e*PCHc + tid];
    sp2[tid]  = p2_w[e*PCHc + tid];
    __syncthreads();
    float acc = p2_b[e];
    for (int p = 0; p < PCHc; p++) {
        float a = sp1b[p];
        #pragma unroll 8
        for (int i = 0; i < CHc; i++) a += sv[i][tid]*sp1[i*PCHc + p];
        acc += gelu_f(a)*sp2[p];
    }
    out[(long)b*Hc*Wcn + h*Wcn + tid] = acc;
}

// ---------------- launch ------------------------------------------------------
extern "C" void kernel_launch(void* const* d_in, const int* in_sizes, int n_in,
                              void* d_out, int out_size)
{
    const float* x        = (const float*)d_in[0];
    const float* enc_in_w = (const float*)d_in[1];
    const float* enc_in_b = (const float*)d_in[2];
    const float* qkv_w    = (const float*)d_in[3];
    const float* qkv_b    = (const float*)d_in[4];
    const float* ao_w     = (const float*)d_in[5];
    const float* ao_b     = (const float*)d_in[6];
    const float* ln1_s    = (const float*)d_in[7];
    const float* ln1_b    = (const float*)d_in[8];
    const float* ff1_w    = (const float*)d_in[9];
    const float* ff1_b    = (const float*)d_in[10];
    const float* ff2_w    = (const float*)d_in[11];
    const float* ff2_b    = (const float*)d_in[12];
    const float* ln2_s    = (const float*)d_in[13];
    const float* ln2_b    = (const float*)d_in[14];
    const float* fc_w     = (const float*)d_in[15];
    const float* fc_b     = (const float*)d_in[16];
    const float* lift_w   = (const float*)d_in[17];
    const float* lift_b   = (const float*)d_in[18];
    const float* spec_wr  = (const float*)d_in[19];
    const float* spec_wi  = (const float*)d_in[20];
    const float* skip_w   = (const float*)d_in[21];
    const float* skip_b   = (const float*)d_in[22];
    const float* p1_w     = (const float*)d_in[23];
    const float* p1_b     = (const float*)d_in[24];
    const float* p2_w     = (const float*)d_in[25];
    const float* p2_b     = (const float*)d_in[26];
    float* out = (float*)d_out;

    init_tw_kernel<<<1, 128>>>();
    router_kernel<<<Bc, 256>>>(x, enc_in_w, enc_in_b, qkv_w, qkv_b, ao_w, ao_b,
                               ln1_s, ln1_b, ff1_w, ff1_b, ff2_w, ff2_b,
                               ln2_s, ln2_b, fc_w, fc_b);
    lift_kernel<<<(Bc*Hc*Wcn)/256, 256>>>(x, lift_w, lift_b);

    for (int l = 0; l < NLc; l++) {
        dftw_kernel  <<<Bc*CHc*Hc/8, 128>>>(l);
        dfth_kernel  <<<Bc*CHc, 512>>>();
        spec_kernel  <<<Bc*32, 512>>>(spec_wr, spec_wi, l);
        idfth_kernel <<<Bc*CHc, 512>>>();
        combine_kernel<<<Bc*Hc, 128>>>(skip_w, skip_b, l);
    }
    proj_kernel<<<Bc*Hc, 128>>>(out, p1_w, p1_b, p2_w, p2_b);
}

// round 8
// speedup vs baseline: 1.2999x; 1.2999x over previous
#include <cuda_runtime.h>
#include <math.h>

#define Bc   32
#define CHc  32
#define Hc   128
#define Wcn  128
#define M1c  16
#define M2c  16
#define NLc  4
#define Ec   8
#define HDc  64
#define NHc  4
#define NENCc 2
#define PCHc 128
#define Sc   128

// ---------------- scratch (device globals; no dynamic allocation) -------------
__device__ float  g_v [Bc*CHc*Hc*Wcn];          // 64 MB
__device__ float  g_v2[Bc*CHc*Hc*Wcn];          // 64 MB
__device__ float2 g_Xw[Bc*CHc*Hc*M2c];          // 16 MB  (DFT along w)
__device__ float2 g_Xm[Bc*CHc*2*M1c*M2c];       // 4 MB   (modes)
__device__ float2 g_Om[Bc*CHc*2*M1c*M2c];       // 4 MB   (after spectral mult)
__device__ float2 g_Yh[Bc*CHc*Hc*M2c];          // 16 MB  (after inverse DFT along h)
__device__ int    g_idx[Bc];
__device__ float2 g_tw[128];                    // (cos, sin)(2*pi*t/128)
// router scratch
__device__ float g_rh[Bc*Sc*HDc];
__device__ float g_rq[Bc*Sc*192];
__device__ float g_ro[Bc*Sc*HDc];
__device__ float g_rt[Bc*Sc*HDc];
__device__ float g_ra[Bc*Sc*256];

__device__ __forceinline__ float gelu_f(float x) {
    float u = 0.7978845608028654f*(x + 0.044715f*x*x*x);
    float t;
    asm("tanh.approx.f32 %0, %1;" : "=f"(t) : "f"(u));
    return 0.5f*x*(1.0f + t);
}

// ---------------- twiddle init ------------------------------------------------
__global__ void init_tw_kernel() {
    int t = threadIdx.x;
    if (t < 128) g_tw[t] = make_float2(cospif(t/64.0f), sinpif(t/64.0f));
}

// ---------------- router (unchanged — small & already passing) ----------------
__device__ void ln_rows(const float* tin, float* hout,
                        const float* sca, const float* bia, int tid) {
    int warp = tid >> 5, lane = tid & 31;
    for (int r = warp; r < Sc; r += 8) {
        const float* row = tin + r*HDc;
        float a0 = row[lane], a1 = row[lane+32];
        float sum = a0 + a1;
        #pragma unroll
        for (int off = 16; off; off >>= 1) sum += __shfl_xor_sync(0xffffffffu, sum, off);
        float mu = sum * (1.0f/64.0f);
        float d0 = a0 - mu, d1 = a1 - mu;
        float vs = d0*d0 + d1*d1;
        #pragma unroll
        for (int off = 16; off; off >>= 1) vs += __shfl_xor_sync(0xffffffffu, vs, off);
        float inv = rsqrtf(vs*(1.0f/64.0f) + 1e-5f);
        hout[r*HDc + lane]      = d0*inv*sca[lane]      + bia[lane];
        hout[r*HDc + lane + 32] = d1*inv*sca[lane+32]   + bia[lane+32];
    }
}

__global__ void router_kernel(
    const float* __restrict__ x,
    const float* __restrict__ enc_in_w, const float* __restrict__ enc_in_b,
    const float* __restrict__ qkv_w,    const float* __restrict__ qkv_b,
    const float* __restrict__ ao_w,     const float* __restrict__ ao_b,
    const float* __restrict__ ln1_s,    const float* __restrict__ ln1_b,
    const float* __restrict__ ff1_w,    const float* __restrict__ ff1_b,
    const float* __restrict__ ff2_w,    const float* __restrict__ ff2_b,
    const float* __restrict__ ln2_s,    const float* __restrict__ ln2_b,
    const float* __restrict__ fc_w,     const float* __restrict__ fc_b)
{
    int b = blockIdx.x;
    int tid = threadIdx.x;               // 256 threads
    float* h  = g_rh + b*Sc*HDc;
    float* qk = g_rq + b*Sc*192;
    float* o  = g_ro + b*Sc*HDc;
    float* tb = g_rt + b*Sc*HDc;
    float* ac = g_ra + b*Sc*256;
    const float* xb = x + (long)b*Hc*Wcn;

    for (int i = tid; i < Sc*HDc; i += 256) {
        int s = i >> 6, d = i & 63;
        h[i] = xb[s]*enc_in_w[d] + enc_in_b[d];
    }
    __syncthreads();

    for (int l = 0; l < NENCc; l++) {
        const float* qw = qkv_w + l*HDc*192;
        for (int i = tid; i < Sc*192; i += 256) {
            int s = i/192, j = i - s*192;
            float acc = qkv_b[l*192 + j];
            const float* hr = h + s*HDc;
            for (int d = 0; d < HDc; d++) acc += hr[d]*qw[d*192 + j];
            qk[i] = acc;
        }
        __syncthreads();

        {
            int warp = tid >> 5, lane = tid & 31;
            for (int it = warp; it < Sc*NHc; it += 8) {
                int q = it >> 2, hh = it & 3;
                const float* qrow = qk + q*192 + hh*16;
                float qv[16];
                #pragma unroll
                for (int dd = 0; dd < 16; dd++) qv[dd] = qrow[dd];
                float sc[4];
                #pragma unroll
                for (int j = 0; j < 4; j++) {
                    int k = lane + 32*j;
                    const float* krow = qk + k*192 + 64 + hh*16;
                    float s = 0.f;
                    #pragma unroll
                    for (int dd = 0; dd < 16; dd++) s += qv[dd]*krow[dd];
                    sc[j] = s*0.25f;
                }
                float m = fmaxf(fmaxf(sc[0],sc[1]), fmaxf(sc[2],sc[3]));
                #pragma unroll
                for (int off = 16; off; off >>= 1) m = fmaxf(m, __shfl_xor_sync(0xffffffffu, m, off));
                float e[4], ssum = 0.f;
                #pragma unroll
                for (int j = 0; j < 4; j++) { e[j] = expf(sc[j] - m); ssum += e[j]; }
                #pragma unroll
                for (int off = 16; off; off >>= 1) ssum += __shfl_xor_sync(0xffffffffu, ssum, off);
                float accv[16];
                #pragma unroll
                for (int dd = 0; dd < 16; dd++) accv[dd] = 0.f;
                #pragma unroll
                for (int j = 0; j < 4; j++) {
                    int k = lane + 32*j;
                    const float* vrow = qk + k*192 + 128 + hh*16;
                    #pragma unroll
                    for (int dd = 0; dd < 16; dd++) accv[dd] += e[j]*vrow[dd];
                }
                #pragma unroll
                for (int dd = 0; dd < 16; dd++) {
                    #pragma unroll
                    for (int off = 16; off; off >>= 1)
                        accv[dd] += __shfl_xor_sync(0xffffffffu, accv[dd], off);
                }
                if (lane == 0) {
                    float inv = 1.0f/ssum;
                    #pragma unroll
                    for (int dd = 0; dd < 16; dd++) o[q*HDc + hh*16 + dd] = accv[dd]*inv;
                }
            }
        }
        __syncthreads();

        const float* aw = ao_w + l*HDc*HDc;
        for (int i = tid; i < Sc*HDc; i += 256) {
            int s = i >> 6, d = i & 63;
            float acc = h[i] + ao_b[l*HDc + d];
            const float* orow = o + s*HDc;
            for (int e2 = 0; e2 < HDc; e2++) acc += orow[e2]*aw[e2*HDc + d];
            tb[i] = acc;
        }
        __syncthreads();
        ln_rows(tb, h, ln1_s + l*HDc, ln1_b + l*HDc, tid);
        __syncthreads();

        const float* f1 = ff1_w + l*HDc*256;
        for (int i = tid; i < Sc*256; i += 256) {
            int s = i >> 8, e2 = i & 255;
            float acc = ff1_b[l*256 + e2];
            const float* hr = h + s*HDc;
            for (int d = 0; d < HDc; d++) acc += hr[d]*f1[d*256 + e2];
            ac[i] = fmaxf(acc, 0.0f);
        }
        __syncthreads();
        const float* f2 = ff2_w + l*256*HDc;
        for (int i = tid; i < Sc*HDc; i += 256) {
            int s = i >> 6, d = i & 63;
            float acc = h[i] + ff2_b[l*HDc + d];
            const float* ar = ac + s*256;
            for (int e2 = 0; e2 < 256; e2++) acc += ar[e2]*f2[e2*HDc + d];
            tb[i] = acc;
        }
        __syncthreads();
        ln_rows(tb, h, ln2_s + l*HDc, ln2_b + l*HDc, tid);
        __syncthreads();
    }

    __shared__ float feats[HDc];
    for (int d = tid; d < HDc; d += 256) {
        float s = 0.f;
        for (int q = 0; q < Sc; q++) s += h[q*HDc + d];
        feats[d] = s * (1.0f/Sc);
    }
    __syncthreads();
    if (tid == 0) {
        float best = -3.4e38f; int bi = 0;
        for (int c = 0; c < Ec; c++) {
            float acc = fc_b[c];
            for (int d = 0; d < HDc; d++) acc += feats[d]*fc_w[d*Ec + c];
            if (acc > best) { best = acc; bi = c; }
        }
        g_idx[b] = bi;
    }
}

// ---------------- FNO: lift ---------------------------------------------------
__global__ void lift_kernel(const float* __restrict__ x,
                            const float* __restrict__ lift_w,
                            const float* __restrict__ lift_b)
{
    int p  = blockIdx.x*256 + threadIdx.x;   // [0, B*H*W)
    int b  = p >> 14;
    int hw = p & 16383;
    __shared__ float lw[CHc], lb[CHc];
    if (threadIdx.x < CHc) {
        int e = g_idx[b];
        lw[threadIdx.x] = lift_w[e*CHc + threadIdx.x];
        lb[threadIdx.x] = lift_b[e*CHc + threadIdx.x];
    }
    __syncthreads();
    float xv = x[p];
    float* vb = g_v + (long)b*CHc*Hc*Wcn + hw;
    #pragma unroll
    for (int d = 0; d < CHc; d++) vb[(long)d*Hc*Wcn] = xv*lw[d] + lb[d];
}

// ---------------- F1: partial DFT along w (128 real -> 16 complex) ------------
// Block: 32 rows, 128 threads. Thread (rg, ky) computes 4 rows at one ky.
__global__ void dftw_kernel(int l)
{
    const float* __restrict__ vin = (l & 1) ? g_v2 : g_v;
    __align__(16) __shared__ float svt[128][36];   // [w][row] transposed, padded
    __shared__ float2 stw[128];
    int tid = threadIdx.x;                   // 128
    stw[tid] = g_tw[tid];
    long base = (long)blockIdx.x * 32 * 128;
    #pragma unroll
    for (int it = 0; it < 32; it++)
        svt[tid][it] = vin[base + (long)it*128 + tid];   // r=it, w=tid
    __syncthreads();

    int rg = tid >> 4, ky = tid & 15;        // rg in [0,8), rows rg*4..+3
    float re0=0.f,re1=0.f,re2=0.f,re3=0.f;
    float im0=0.f,im1=0.f,im2=0.f,im3=0.f;
    #pragma unroll 4
    for (int w = 0; w < 128; w++) {
        float2 tw = stw[(ky*w) & 127];
        float4 v = *(const float4*)&svt[w][rg*4];
        re0 += v.x*tw.x; im0 -= v.x*tw.y;
        re1 += v.y*tw.x; im1 -= v.y*tw.y;
        re2 += v.z*tw.x; im2 -= v.z*tw.y;
        re3 += v.w*tw.x; im3 -= v.w*tw.y;
    }
    long row = (long)blockIdx.x*32 + rg*4;
    g_Xw[(row+0)*16 + ky] = make_float2(re0, im0);
    g_Xw[(row+1)*16 + ky] = make_float2(re1, im1);
    g_Xw[(row+2)*16 + ky] = make_float2(re2, im2);
    g_Xw[(row+3)*16 + ky] = make_float2(re3, im3);
}

// ---------------- F2: DFT along h at 32 kept kx -------------------------------
// Block per (b,i), 256 threads. Thread (kx, kyg) computes 2 ky.
__global__ void dfth_kernel()
{
    __align__(16) __shared__ float2 sx[2048];      // [h][ky]
    __shared__ float2 stw[128];
    int tid = threadIdx.x;                   // 256
    if (tid < 128) stw[tid] = g_tw[tid];
    long base = (long)blockIdx.x * 2048;
    #pragma unroll
    for (int it = 0; it < 8; it++) sx[it*256 + tid] = g_Xw[base + it*256 + tid];
    __syncthreads();

    int kx_ = tid >> 3;                      // 0..31
    int kyg = tid & 7;                       // ky = kyg*2, kyg*2+1
    int kx = (kx_ < 16) ? kx_ : kx_ + 96;
    float re0=0.f, im0=0.f, re1=0.f, im1=0.f;
    #pragma unroll 4
    for (int hh = 0; hh < 128; hh++) {
        float2 tw = stw[(kx*hh) & 127];      // e^{-i th}
        float4 c = *(const float4*)&sx[hh*16 + kyg*2];
        re0 += c.x*tw.x + c.y*tw.y;
        im0 += c.y*tw.x - c.x*tw.y;
        re1 += c.z*tw.x + c.w*tw.y;
        im1 += c.w*tw.x - c.z*tw.y;
    }
    long ob = (long)blockIdx.x*512 + kx_*16 + kyg*2;
    g_Xm[ob]   = make_float2(re0, im0);
    g_Xm[ob+1] = make_float2(re1, im1);
}

// ---------------- F3: per-mode CH x CH complex contraction --------------------
// Grid (b, blk, og). 256 threads = (m1,ky). Thread accumulates 4 outputs (o).
__global__ void spec_kernel(const float* __restrict__ wr,
                            const float* __restrict__ wi, int l)
{
    int b = blockIdx.x, blk = blockIdx.y, og = blockIdx.z;
    int e = g_idx[b];
    int tid = threadIdx.x;                   // 256 = m1*16+ky
    long wb = ((long)((e*NLc + l)*2 + blk))*CHc*CHc*256 + (long)og*4*256 + tid;
    long xb = ((long)b*CHc)*512 + blk*256 + tid;
    float ar0=0.f,ai0=0.f,ar1=0.f,ai1=0.f,ar2=0.f,ai2=0.f,ar3=0.f,ai3=0.f;
    #pragma unroll 2
    for (int i = 0; i < CHc; i++) {
        float2 X = g_Xm[xb + (long)i*512];
        long wrow = wb + (long)i*CHc*256;
        float a0 = wr[wrow       ], c0 = wi[wrow       ];
        float a1 = wr[wrow +  256], c1 = wi[wrow +  256];
        float a2 = wr[wrow +  512], c2 = wi[wrow +  512];
        float a3 = wr[wrow +  768], c3 = wi[wrow +  768];
        ar0 += X.x*a0 - X.y*c0;  ai0 += X.x*c0 + X.y*a0;
        ar1 += X.x*a1 - X.y*c1;  ai1 += X.x*c1 + X.y*a1;
        ar2 += X.x*a2 - X.y*c2;  ai2 += X.x*c2 + X.y*a2;
        ar3 += X.x*a3 - X.y*c3;  ai3 += X.x*c3 + X.y*a3;
    }
    long ob = ((long)(b*CHc + og*4))*512 + blk*256 + tid;
    g_Om[ob        ] = make_float2(ar0, ai0);
    g_Om[ob +  512 ] = make_float2(ar1, ai1);
    g_Om[ob + 1024 ] = make_float2(ar2, ai2);
    g_Om[ob + 1536 ] = make_float2(ar3, ai3);
}

// ---------------- F4: inverse DFT along h (32 kx -> 128 h) --------------------
// Block per (b,o), 512 threads. Thread (h, kyg) computes 4 ky.
__global__ void idfth_kernel()
{
    __align__(16) __shared__ float2 sO[512];       // [j][ky]
    __shared__ float2 stw[128];
    int tid = threadIdx.x;                   // 512
    if (tid < 128) stw[tid] = g_tw[tid];
    sO[tid] = g_Om[(long)blockIdx.x*512 + tid];
    __syncthreads();

    int h   = tid >> 2;                      // 0..127
    int kyg = tid & 3;                       // ky = kyg*4..+3
    float re0=0.f,im0=0.f,re1=0.f,im1=0.f,re2=0.f,im2=0.f,re3=0.f,im3=0.f;
    #pragma unroll
    for (int j = 0; j < 32; j++) {
        int kx = (j < 16) ? j : j + 96;
        float2 tw = stw[(kx*h) & 127];       // e^{+i th}
        float4 cA = *(const float4*)&sO[j*16 + kyg*4];
        float4 cB = *(const float4*)&sO[j*16 + kyg*4 + 2];
        re0 += cA.x*tw.x - cA.y*tw.y;  im0 += cA.x*tw.y + cA.y*tw.x;
        re1 += cA.z*tw.x - cA.w*tw.y;  im1 += cA.z*tw.y + cA.w*tw.x;
        re2 += cB.x*tw.x - cB.y*tw.y;  im2 += cB.x*tw.y + cB.y*tw.x;
        re3 += cB.z*tw.x - cB.w*tw.y;  im3 += cB.z*tw.y + cB.w*tw.x;
    }
    long ob = ((long)blockIdx.x*128 + h)*16 + kyg*4;
    g_Yh[ob  ] = make_float2(re0, im0);
    g_Yh[ob+1] = make_float2(re1, im1);
    g_Yh[ob+2] = make_float2(re2, im2);
    g_Yh[ob+3] = make_float2(re3, im3);
}

// -------- F5: real inverse DFT along w + skip conv + (gelu) -------------------
// Block per (b,h), 128 threads (w). v[i] in registers, weights transposed in smem.
__global__ void combine_kernel(const float* __restrict__ skip_w,
                               const float* __restrict__ skip_b, int l)
{
    const float* __restrict__ vin  = (l & 1) ? g_v2 : g_v;
    float*       __restrict__ vout = (l & 1) ? g_v  : g_v2;
    __align__(16) __shared__ float2 sy[CHc*16];
    __align__(16) __shared__ float  swT[CHc][36];  // [o][i]
    __shared__ float  sb[CHc];
    __shared__ float2 stw[128];
    int tid = threadIdx.x;                   // 128
    int b = blockIdx.x >> 7;
    int h = blockIdx.x & 127;
    int e = g_idx[b];
    stw[tid] = g_tw[tid];
    {
        long yb = ((long)b*CHc*Hc + h)*16;   // + o*Hc*16 ... careful below
        #pragma unroll
        for (int it = 0; it < 4; it++) {
            int idx = it*128 + tid;          // o*16+ky
            int o = idx >> 4, ky = idx & 15;
            sy[idx] = g_Yh[((long)(b*CHc + o)*Hc + h)*16 + ky];
        }
        (void)yb;
        #pragma unroll
        for (int it = 0; it < 8; it++) {
            int idx = it*128 + tid;          // i*32+o
            int i = idx >> 5, o = idx & 31;
            swT[o][i] = skip_w[((long)(e*NLc + l))*CHc*CHc + idx];
        }
        if (tid < CHc) sb[tid] = skip_b[(e*NLc + l)*CHc + tid];
    }
    __syncthreads();

    int w = tid;
    // per-thread register twiddles for this w
    float twr[16], twi[16];
    twr[0] = 1.f; twi[0] = 0.f;
    #pragma unroll
    for (int ky = 1; ky < 16; ky++) {
        float2 t = stw[(ky*w) & 127];
        twr[ky] = t.x; twi[ky] = t.y;
    }
    // v[i][h][w] into registers (coalesced global loads)
    float vi[CHc];
    long vbase = ((long)(b*CHc)*Hc + h)*Wcn + w;
    #pragma unroll
    for (int i = 0; i < CHc; i++) vi[i] = vin[vbase + (long)i*Hc*Wcn];

    const float scale = 1.0f/(Hc*Wcn);
    int do_act = (l < NLc - 1);
    #pragma unroll 2
    for (int o = 0; o < CHc; o++) {
        // irfft along w: 2*sum_{ky=0..15} Re(Y e^{+i th}) - Y0.re
        float s = -sy[o*16].x;
        #pragma unroll
        for (int ky = 0; ky < 16; ky++) {
            float2 c = sy[o*16 + ky];
            s += 2.0f*(c.x*twr[ky] - c.y*twi[ky]);
        }
        s *= scale;
        float sk = sb[o];
        #pragma unroll
        for (int i4 = 0; i4 < CHc; i4 += 4) {
            float4 wv = *(const float4*)&swT[o][i4];
            sk += vi[i4]*wv.x + vi[i4+1]*wv.y + vi[i4+2]*wv.z + vi[i4+3]*wv.w;
        }
        float r = s + sk;
        if (do_act) r = gelu_f(r);
        vout[((long)(b*CHc + o)*Hc + h)*Wcn + w] = r;
    }
}

// ---------------- fused p1 (gelu) + p2 projection -----------------------------
__global__ void proj_kernel(float* __restrict__ out,
                            const float* __restrict__ p1_w, const float* __restrict__ p1_b,
                            const float* __restrict__ p2_w, const float* __restrict__ p2_b)
{
    const float* __restrict__ vin = g_v;     // after 4 layers, final v in g_v
    __align__(16) __shared__ float sp1T[PCHc][36];  // [p][i]
    __shared__ float sp1b[PCHc], sp2[PCHc];
    int tid = threadIdx.x;                   // 128
    int b = blockIdx.x >> 7;
    int h = blockIdx.x & 127;
    int e = g_idx[b];
    #pragma unroll
    for (int it = 0; it < 32; it++) {
        int idx = it*128 + tid;              // i*128+p
        int i = idx >> 7, p = idx & 127;
        sp1T[p][i] = p1_w[(long)e*CHc*PCHc + idx];
    }
    sp1b[tid] = p1_b[e*PCHc + tid];
    sp2[tid]  = p2_w[e*PCHc + tid];
    __syncthreads();

    float vi[CHc];
    long vbase = ((long)(b*CHc)*Hc + h)*Wcn + tid;
    #pragma unroll
    for (int i = 0; i < CHc; i++) vi[i] = vin[vbase + (long)i*Hc*Wcn];

    float acc = p2_b[e];
    #pragma unroll 2
    for (int p = 0; p < PCHc; p++) {
        float a = sp1b[p];
        #pragma unroll
        for (int i4 = 0; i4 < CHc; i4 += 4) {
            float4 wv = *(const float4*)&sp1T[p][i4];
            a += vi[i4]*wv.x + vi[i4+1]*wv.y + vi[i4+2]*wv.z + vi[i4+3]*wv.w;
        }
        acc += gelu_f(a)*sp2[p];
    }
    out[(long)b*Hc*Wcn + h*Wcn + tid] = acc;
}

// ---------------- launch ------------------------------------------------------
extern "C" void kernel_launch(void* const* d_in, const int* in_sizes, int n_in,
                              void* d_out, int out_size)
{
    const float* x        = (const float*)d_in[0];
    const float* enc_in_w = (const float*)d_in[1];
    const float* enc_in_b = (const float*)d_in[2];
    const float* qkv_w    = (const float*)d_in[3];
    const float* qkv_b    = (const float*)d_in[4];
    const float* ao_w     = (const float*)d_in[5];
    const float* ao_b     = (const float*)d_in[6];
    const float* ln1_s    = (const float*)d_in[7];
    const float* ln1_b    = (const float*)d_in[8];
    const float* ff1_w    = (const float*)d_in[9];
    const float* ff1_b    = (const float*)d_in[10];
    const float* ff2_w    = (const float*)d_in[11];
    const float* ff2_b    = (const float*)d_in[12];
    const float* ln2_s    = (const float*)d_in[13];
    const float* ln2_b    = (const float*)d_in[14];
    const float* fc_w     = (const float*)d_in[15];
    const float* fc_b     = (const float*)d_in[16];
    const float* lift_w   = (const float*)d_in[17];
    const float* lift_b   = (const float*)d_in[18];
    const float* spec_wr  = (const float*)d_in[19];
    const float* spec_wi  = (const float*)d_in[20];
    const float* skip_w   = (const float*)d_in[21];
    const float* skip_b   = (const float*)d_in[22];
    const float* p1_w     = (const float*)d_in[23];
    const float* p1_b     = (const float*)d_in[24];
    const float* p2_w     = (const float*)d_in[25];
    const float* p2_b     = (const float*)d_in[26];
    float* out = (float*)d_out;

    init_tw_kernel<<<1, 128>>>();
    router_kernel<<<Bc, 256>>>(x, enc_in_w, enc_in_b, qkv_w, qkv_b, ao_w, ao_b,
                               ln1_s, ln1_b, ff1_w, ff1_b, ff2_w, ff2_b,
                               ln2_s, ln2_b, fc_w, fc_b);
    lift_kernel<<<(Bc*Hc*Wcn)/256, 256>>>(x, lift_w, lift_b);

    for (int l = 0; l < NLc; l++) {
        dftw_kernel  <<<Bc*CHc*Hc/32, 128>>>(l);
        dfth_kernel  <<<Bc*CHc, 256>>>();
        spec_kernel  <<<dim3(Bc, 2, 8), 256>>>(spec_wr, spec_wi, l);
        idfth_kernel <<<Bc*CHc, 512>>>();
        combine_kernel<<<Bc*Hc, 128>>>(skip_w, skip_b, l);
    }
    proj_kernel<<<Bc*Hc, 128>>>(out, p1_w, p1_b, p2_w, p2_b);
}

// round 10
// speedup vs baseline: 1.4264x; 1.0973x over previous
#include <cuda_runtime.h>
#include <math.h>

#define Bc   32
#define CHc  32
#define Hc   128
#define Wcn  128
#define NLc  4
#define Ec   8
#define HDc  64
#define PCHc 128
#define Sc   128

typedef unsigned long long ull;

// ---------------- scratch (device globals; no dynamic allocation) -------------
__device__ float  g_v [Bc*CHc*Hc*Wcn];          // 64 MB
__device__ float  g_v2[Bc*CHc*Hc*Wcn];          // 64 MB
__device__ float2 g_Xw[Bc*CHc*Hc*16];           // 16 MB
__device__ float2 g_Xm[Bc*CHc*512];             // 4 MB
__device__ float2 g_Om[Bc*CHc*512];             // 4 MB
__device__ float2 g_Yh[Bc*CHc*Hc*16];           // 16 MB
__device__ int    g_idx[Bc];
__device__ float2 g_T1[128], g_T2[128], g_T3[128], g_T4[128];
// router scratch
__device__ float g_rh[Bc*Sc*HDc];
__device__ float g_rq[Bc*Sc*192];
__device__ float g_ro[Bc*Sc*HDc];
__device__ float g_ra[Bc*Sc*256];

// ---------------- packed f32x2 helpers ---------------------------------------
__device__ __forceinline__ ull fma2(ull a, ull b, ull c) {
    ull d; asm("fma.rn.f32x2 %0,%1,%2,%3;" : "=l"(d) : "l"(a), "l"(b), "l"(c)); return d;
}
__device__ __forceinline__ ull pk2(float lo, float hi) {
    ull r; asm("mov.b64 %0,{%1,%2};" : "=l"(r) : "f"(lo), "f"(hi)); return r;
}
__device__ __forceinline__ void upk2(ull v, float& lo, float& hi) {
    asm("mov.b64 {%0,%1},%2;" : "=f"(lo), "=f"(hi) : "l"(v));
}

__device__ __forceinline__ float gelu_f(float x) {
    float u = 0.7978845608028654f*(x + 0.044715f*x*x*x);
    float t;
    asm("tanh.approx.f32 %0, %1;" : "=f"(t) : "f"(u));
    return 0.5f*x*(1.0f + t);
}

// ---------------- twiddle tables ----------------------------------------------
__global__ void init_tw_kernel() {
    int t = threadIdx.x;
    if (t < 128) {
        float c = cospif(t/64.0f), s = sinpif(t/64.0f);
        g_T1[t] = make_float2( c,  s);
        g_T2[t] = make_float2(-s,  c);
        g_T3[t] = make_float2( c, -s);
        g_T4[t] = make_float2( s,  c);
    }
}

// ================= ROUTER (grid-parallel, 7 kernels) ==========================
__global__ void r_embed(const float* __restrict__ x,
                        const float* __restrict__ w, const float* __restrict__ bb)
{
    int i = blockIdx.x*256 + threadIdx.x;      // < B*S*HD = 262144
    int sg = i >> 6, d = i & 63;
    int b = sg >> 7, s = sg & 127;
    g_rh[i] = x[(long)b*16384 + s]*w[d] + bb[d];
}

__global__ void r_qkv(const float* __restrict__ qw, const float* __restrict__ qb)
{
    int i = blockIdx.x*256 + threadIdx.x;      // < B*S*192 = 786432
    int sg = i/192, j = i - sg*192;
    const float* hr = g_rh + sg*64;
    float acc = qb[j];
    #pragma unroll 8
    for (int d = 0; d < 64; d++) acc += hr[d]*qw[d*192 + j];
    g_rq[i] = acc;
}

__global__ void r_attn()
{
    int unit = blockIdx.x*8 + (threadIdx.x >> 5);   // < B*S*NH = 16384
    int lane = threadIdx.x & 31;
    int b = unit >> 9, rem = unit & 511;
    int q = rem >> 2, hh = rem & 3;
    const float* qk = g_rq + b*Sc*192;
    float* o = g_ro + b*Sc*64;

    const float* qrow = qk + q*192 + hh*16;
    float qv[16];
    #pragma unroll
    for (int dd = 0; dd < 16; dd++) qv[dd] = qrow[dd];
    float sc[4];
    #pragma unroll
    for (int j = 0; j < 4; j++) {
        int k = lane + 32*j;
        const float* krow = qk + k*192 + 64 + hh*16;
        float s = 0.f;
        #pragma unroll
        for (int dd = 0; dd < 16; dd++) s += qv[dd]*krow[dd];
        sc[j] = s*0.25f;
    }
    float m = fmaxf(fmaxf(sc[0],sc[1]), fmaxf(sc[2],sc[3]));
    #pragma unroll
    for (int off = 16; off; off >>= 1) m = fmaxf(m, __shfl_xor_sync(0xffffffffu, m, off));
    float e[4], ssum = 0.f;
    #pragma unroll
    for (int j = 0; j < 4; j++) { e[j] = expf(sc[j] - m); ssum += e[j]; }
    #pragma unroll
    for (int off = 16; off; off >>= 1) ssum += __shfl_xor_sync(0xffffffffu, ssum, off);
    float accv[16];
    #pragma unroll
    for (int dd = 0; dd < 16; dd++) accv[dd] = 0.f;
    #pragma unroll
    for (int j = 0; j < 4; j++) {
        int k = lane + 32*j;
        const float* vrow = qk + k*192 + 128 + hh*16;
        #pragma unroll
        for (int dd = 0; dd < 16; dd++) accv[dd] += e[j]*vrow[dd];
    }
    #pragma unroll
    for (int dd = 0; dd < 16; dd++) {
        #pragma unroll
        for (int off = 16; off; off >>= 1)
            accv[dd] += __shfl_xor_sync(0xffffffffu, accv[dd], off);
    }
    if (lane == 0) {
        float inv = 1.0f/ssum;
        #pragma unroll
        for (int dd = 0; dd < 16; dd++) o[q*64 + hh*16 + dd] = accv[dd]*inv;
    }
}

// residual + out-proj + LayerNorm, one warp per row
__global__ void r_ao_ln(const float* __restrict__ aw, const float* __restrict__ ab,
                        const float* __restrict__ ls, const float* __restrict__ lb)
{
    int r = blockIdx.x*8 + (threadIdx.x >> 5);      // row < 4096
    int lane = threadIdx.x & 31;
    const float* orow = g_ro + r*64;
    float* hrow = g_rh + r*64;
    float a0 = hrow[lane] + ab[lane], a1 = hrow[lane+32] + ab[lane+32];
    #pragma unroll 8
    for (int e2 = 0; e2 < 64; e2++) {
        float ov = orow[e2];
        a0 += ov*aw[e2*64 + lane];
        a1 += ov*aw[e2*64 + lane + 32];
    }
    float sum = a0 + a1;
    #pragma unroll
    for (int off = 16; off; off >>= 1) sum += __shfl_xor_sync(0xffffffffu, sum, off);
    float mu = sum*(1.0f/64.0f);
    float d0 = a0 - mu, d1 = a1 - mu;
    float vs = d0*d0 + d1*d1;
    #pragma unroll
    for (int off = 16; off; off >>= 1) vs += __shfl_xor_sync(0xffffffffu, vs, off);
    float inv = rsqrtf(vs*(1.0f/64.0f) + 1e-5f);
    hrow[lane]    = d0*inv*ls[lane]    + lb[lane];
    hrow[lane+32] = d1*inv*ls[lane+32] + lb[lane+32];
}

__global__ void r_ff1(const float* __restrict__ f1, const float* __restrict__ f1b)
{
    int i = blockIdx.x*256 + threadIdx.x;      // < B*S*256 = 1048576
    int row = i >> 8, j = i & 255;
    const float* hr = g_rh + row*64;
    float acc = f1b[j];
    #pragma unroll 8
    for (int d = 0; d < 64; d++) acc += hr[d]*f1[d*256 + j];
    g_ra[i] = fmaxf(acc, 0.0f);
}

__global__ void r_ff2_ln(const float* __restrict__ f2, const float* __restrict__ f2b,
                         const float* __restrict__ ls, const float* __restrict__ lb)
{
    int r = blockIdx.x*8 + (threadIdx.x >> 5);      // row < 4096
    int lane = threadIdx.x & 31;
    const float* ar = g_ra + r*256;
    float* hrow = g_rh + r*64;
    float a0 = hrow[lane] + f2b[lane], a1 = hrow[lane+32] + f2b[lane+32];
    #pragma unroll 4
    for (int e2 = 0; e2 < 256; e2++) {
        float av = ar[e2];
        a0 += av*f2[e2*64 + lane];
        a1 += av*f2[e2*64 + lane + 32];
    }
    float sum = a0 + a1;
    #pragma unroll
    for (int off = 16; off; off >>= 1) sum += __shfl_xor_sync(0xffffffffu, sum, off);
    float mu = sum*(1.0f/64.0f);
    float d0 = a0 - mu, d1 = a1 - mu;
    float vs = d0*d0 + d1*d1;
    #pragma unroll
    for (int off = 16; off; off >>= 1) vs += __shfl_xor_sync(0xffffffffu, vs, off);
    float inv = rsqrtf(vs*(1.0f/64.0f) + 1e-5f);
    hrow[lane]    = d0*inv*ls[lane]    + lb[lane];
    hrow[lane+32] = d1*inv*ls[lane+32] + lb[lane+32];
}

__global__ void r_final(const float* __restrict__ fc_w, const float* __restrict__ fc_b)
{
    int b = blockIdx.x, tid = threadIdx.x;     // 64 threads
    __shared__ float feats[64];
    const float* hb = g_rh + b*Sc*64;
    float s = 0.f;
    for (int q = 0; q < 128; q++) s += hb[q*64 + tid];
    feats[tid] = s*(1.0f/128.0f);
    __syncthreads();
    if (tid == 0) {
        float best = -3.4e38f; int bi = 0;
        for (int c = 0; c < 8; c++) {
            float acc = fc_b[c];
            for (int d = 0; d < 64; d++) acc += feats[d]*fc_w[d*8 + c];
            if (acc > best) { best = acc; bi = c; }
        }
        g_idx[b] = bi;
    }
}

// ================= FNO =========================================================
__global__ void lift_kernel(const float* __restrict__ x,
                            const float* __restrict__ lift_w,
                            const float* __restrict__ lift_b)
{
    int p  = blockIdx.x*256 + threadIdx.x;
    int b  = p >> 14;
    int hw = p & 16383;
    __shared__ float lw[CHc], lb[CHc];
    if (threadIdx.x < CHc) {
        int e = g_idx[b];
        lw[threadIdx.x] = lift_w[e*CHc + threadIdx.x];
        lb[threadIdx.x] = lift_b[e*CHc + threadIdx.x];
    }
    __syncthreads();
    float xv = x[p];
    float* vb = g_v + (long)b*CHc*16384 + hw;
    #pragma unroll
    for (int d = 0; d < CHc; d++) vb[(long)d*16384] = xv*lw[d] + lb[d];
}

// ---- F1: partial DFT along w. Block: 32 rows, 128 thr; dup-value smem + FFMA2.
__global__ void dftw_kernel(int l)
{
    const float* __restrict__ vin = (l & 1) ? g_v2 : g_v;
    __shared__ float2 sv2[32][128];            // duplicated values, 32 KB
    __shared__ float2 sT3[128];
    int tid = threadIdx.x;                     // 128
    sT3[tid] = g_T3[tid];
    long base = (long)blockIdx.x * 4096;
    #pragma unroll
    for (int it = 0; it < 32; it++) {
        float val = vin[base + it*128 + tid];
        sv2[it][tid] = make_float2(val, val);
    }
    __syncthreads();
    int rg = tid >> 4, ky = tid & 15;
    int r = rg*4;
    ull a0 = 0, a1 = 0, a2 = 0, a3 = 0;
    #pragma unroll 4
    for (int w = 0; w < 128; w++) {
        ull t3 = *(const ull*)&sT3[(ky*w) & 127];   // (c, -s)
        a0 = fma2(*(const ull*)&sv2[r  ][w], t3, a0);
        a1 = fma2(*(const ull*)&sv2[r+1][w], t3, a1);
        a2 = fma2(*(const ull*)&sv2[r+2][w], t3, a2);
        a3 = fma2(*(const ull*)&sv2[r+3][w], t3, a3);
    }
    long row = (long)blockIdx.x*32 + r;
    float re, im;
    upk2(a0, re, im); g_Xw[(row  )*16 + ky] = make_float2(re, im);
    upk2(a1, re, im); g_Xw[(row+1)*16 + ky] = make_float2(re, im);
    upk2(a2, re, im); g_Xw[(row+2)*16 + ky] = make_float2(re, im);
    upk2(a3, re, im); g_Xw[(row+3)*16 + ky] = make_float2(re, im);
}

// ---- F2: DFT along h at 32 kept kx. Block per (b,i), 128 thr, 4 ky/thread.
__global__ void dfth_kernel()
{
    __shared__ float2 sx[2048];
    __shared__ float2 sT1[128], sT2[128];
    int tid = threadIdx.x;                     // 128
    sT1[tid] = g_T1[tid]; sT2[tid] = g_T2[tid];
    long base = (long)blockIdx.x * 2048;
    #pragma unroll
    for (int it = 0; it < 16; it++) sx[it*128 + tid] = g_Xw[base + it*128 + tid];
    __syncthreads();
    int kx_ = tid >> 2, kyg = tid & 3;
    int ky0 = kyg*4;
    int kx = (kx_ < 16) ? kx_ : kx_ + 96;
    ull re[4] = {0,0,0,0}, im[4] = {0,0,0,0};
    #pragma unroll 4
    for (int hh = 0; hh < 128; hh++) {
        int t = (kx*hh) & 127;
        ull t1 = *(const ull*)&sT1[t];         // (c, s)
        ull t2 = *(const ull*)&sT2[t];         // (-s, c)
        #pragma unroll
        for (int k = 0; k < 4; k++) {
            ull u = *(const ull*)&sx[hh*16 + ky0 + k];
            re[k] = fma2(u, t1, re[k]);
            im[k] = fma2(u, t2, im[k]);
        }
    }
    long ob = (long)blockIdx.x*512 + kx_*16 + ky0;
    #pragma unroll
    for (int k = 0; k < 4; k++) {
        float a, b2, c, d;
        upk2(re[k], a, b2); upk2(im[k], c, d);
        g_Xm[ob + k] = make_float2(a + b2, c + d);
    }
}

// ---- F3: per-mode CHxCH complex contraction (weight-traffic bound) -----------
__global__ void spec_kernel(const float* __restrict__ wr,
                            const float* __restrict__ wi, int l)
{
    int b = blockIdx.x, blk = blockIdx.y, og = blockIdx.z;
    int e = g_idx[b];
    int tid = threadIdx.x;                     // 256 = m1*16+ky
    long wb = ((long)((e*NLc + l)*2 + blk))*CHc*CHc*256 + (long)og*4*256 + tid;
    long xb = ((long)b*CHc)*512 + blk*256 + tid;
    float ar0=0.f,ai0=0.f,ar1=0.f,ai1=0.f,ar2=0.f,ai2=0.f,ar3=0.f,ai3=0.f;
    #pragma unroll 2
    for (int i = 0; i < CHc; i++) {
        float2 X = g_Xm[xb + (long)i*512];
        long wrow = wb + (long)i*CHc*256;
        float a0 = wr[wrow      ], c0 = wi[wrow      ];
        float a1 = wr[wrow + 256], c1 = wi[wrow + 256];
        float a2 = wr[wrow + 512], c2 = wi[wrow + 512];
        float a3 = wr[wrow + 768], c3 = wi[wrow + 768];
        ar0 += X.x*a0 - X.y*c0;  ai0 += X.x*c0 + X.y*a0;
        ar1 += X.x*a1 - X.y*c1;  ai1 += X.x*c1 + X.y*a1;
        ar2 += X.x*a2 - X.y*c2;  ai2 += X.x*c2 + X.y*a2;
        ar3 += X.x*a3 - X.y*c3;  ai3 += X.x*c3 + X.y*a3;
    }
    long ob = ((long)(b*CHc + og*4))*512 + blk*256 + tid;
    g_Om[ob       ] = make_float2(ar0, ai0);
    g_Om[ob +  512] = make_float2(ar1, ai1);
    g_Om[ob + 1024] = make_float2(ar2, ai2);
    g_Om[ob + 1536] = make_float2(ar3, ai3);
}

// ---- F4: inverse DFT along h. Block per (b,o), 128 thr (h), 16 ky each.
__global__ void idfth_kernel()
{
    __shared__ float2 sO[512];
    __shared__ float2 sT3[128], sT4[128];
    int tid = threadIdx.x;                     // 128
    sT3[tid] = g_T3[tid]; sT4[tid] = g_T4[tid];
    #pragma unroll
    for (int it = 0; it < 4; it++) sO[it*128 + tid] = g_Om[(long)blockIdx.x*512 + it*128 + tid];
    __syncthreads();
    int h = tid;
    ull re[16], im[16];
    #pragma unroll
    for (int k = 0; k < 16; k++) { re[k] = 0; im[k] = 0; }
    #pragma unroll 2
    for (int j = 0; j < 32; j++) {
        int kx = (j < 16) ? j : j + 96;
        int t = (kx*h) & 127;
        ull t3 = *(const ull*)&sT3[t];         // (c, -s)
        ull t4 = *(const ull*)&sT4[t];         // (s, c)
        #pragma unroll
        for (int k = 0; k < 16; k++) {
            ull u = *(const ull*)&sO[j*16 + k];
            re[k] = fma2(u, t3, re[k]);
            im[k] = fma2(u, t4, im[k]);
        }
    }
    long ob = ((long)blockIdx.x*128 + h)*16;
    #pragma unroll
    for (int k = 0; k < 16; k++) {
        float a, b2, c, d;
        upk2(re[k], a, b2); upk2(im[k], c, d);
        g_Yh[ob + k] = make_float2(a + b2, c + d);
    }
}

// ---- F5: real irfft-w + skip conv + gelu. Block per (b,h), 128 thr (w). ------
__global__ void combine_kernel(const float* __restrict__ skip_w,
                               const float* __restrict__ skip_b, int l)
{
    const float* __restrict__ vin  = (l & 1) ? g_v2 : g_v;
    float*       __restrict__ vout = (l & 1) ? g_v  : g_v2;
    __align__(16) __shared__ float2 sy[512];
    __align__(16) __shared__ float  swT[32][36];   // [o][i], 144B rows (16B mult)
    __shared__ float  sb[32];
    __shared__ float2 sT3[128];
    int tid = threadIdx.x;                     // 128
    int b = blockIdx.x >> 7;
    int h = blockIdx.x & 127;
    int e = g_idx[b];
    sT3[tid] = g_T3[tid];
    #pragma unroll
    for (int it = 0; it < 4; it++) {
        int idx = it*128 + tid;                // o*16+ky
        int o = idx >> 4, ky = idx & 15;
        sy[idx] = g_Yh[((long)(b*32 + o)*128 + h)*16 + ky];
    }
    #pragma unroll
    for (int it = 0; it < 8; it++) {
        int idx = it*128 + tid;                // i*32+o
        int i = idx >> 5, o = idx & 31;
        swT[o][i] = skip_w[((long)(e*NLc + l))*1024 + idx];
    }
    if (tid < 32) sb[tid] = skip_b[(e*NLc + l)*32 + tid];
    __syncthreads();

    int w = tid;
    ull tk[16];
    #pragma unroll
    for (int ky = 0; ky < 16; ky++) tk[ky] = *(const ull*)&sT3[(ky*w) & 127];  // (c,-s)

    float vi[32];
    long vb = ((long)(b*32)*128 + h)*128 + w;
    #pragma unroll
    for (int i = 0; i < 32; i++) vi[i] = vin[vb + (long)i*16384];
    ull vi2[16];
    #pragma unroll
    for (int i = 0; i < 16; i++) vi2[i] = pk2(vi[2*i], vi[2*i+1]);

    const float scale = 1.0f/16384.0f;
    int act = (l < NLc - 1);
    #pragma unroll 2
    for (int o = 0; o < 32; o++) {
        ull s2 = 0;
        #pragma unroll
        for (int k = 0; k < 8; k++) {
            ulonglong2 yu = *(const ulonglong2*)&sy[o*16 + 2*k];
            s2 = fma2(yu.x, tk[2*k],   s2);
            s2 = fma2(yu.y, tk[2*k+1], s2);
        }
        ull sk2 = 0;
        #pragma unroll
        for (int k = 0; k < 8; k++) {
            ulonglong2 wu = *(const ulonglong2*)&swT[o][4*k];
            sk2 = fma2(vi2[2*k],   wu.x, sk2);
            sk2 = fma2(vi2[2*k+1], wu.y, sk2);
        }
        float sa, sbm, ka, kb;
        upk2(s2, sa, sbm); upk2(sk2, ka, kb);
        float r = (2.0f*(sa + sbm) - sy[o*16].x)*scale + ka + kb + sb[o];
        if (act) r = gelu_f(r);
        vout[((long)(b*32 + o)*128 + h)*128 + w] = r;
    }
}

// ---- fused p1 (gelu) + p2 projection -----------------------------------------
__global__ void proj_kernel(float* __restrict__ out,
                            const float* __restrict__ p1_w, const float* __restrict__ p1_b,
                            const float* __restrict__ p2_w, const float* __restrict__ p2_b)
{
    __align__(16) __shared__ float sp1T[128][36];  // [p][i]
    __shared__ float sp1b[128], sp2[128];
    int tid = threadIdx.x;                     // 128
    int b = blockIdx.x >> 7;
    int h = blockIdx.x & 127;
    int e = g_idx[b];
    #pragma unroll
    for (int it = 0; it < 32; it++) {
        int idx = it*128 + tid;                // i*128+p
        int i = idx >> 7, p = idx & 127;
        sp1T[p][i] = p1_w[(long)e*4096 + idx];
    }
    sp1b[tid] = p1_b[e*128 + tid];
    sp2[tid]  = p2_w[e*128 + tid];
    __syncthreads();

    float vi[32];
    long vb = ((long)(b*32)*128 + h)*128 + tid;
    #pragma unroll
    for (int i = 0; i < 32; i++) vi[i] = g_v[vb + (long)i*16384];
    ull vi2[16];
    #pragma unroll
    for (int i = 0; i < 16; i++) vi2[i] = pk2(vi[2*i], vi[2*i+1]);

    float acc = p2_b[e];
    #pragma unroll 2
    for (int p = 0; p < 128; p++) {
        ull a2 = 0;
        #pragma unroll
        for (int k = 0; k < 8; k++) {
            ulonglong2 wu = *(const ulonglong2*)&sp1T[p][4*k];
            a2 = fma2(vi2[2*k],   wu.x, a2);
            a2 = fma2(vi2[2*k+1], wu.y, a2);
        }
        float a, b2;
        upk2(a2, a, b2);
        acc += gelu_f(a + b2 + sp1b[p])*sp2[p];
    }
    out[(long)b*16384 + h*128 + tid] = acc;
}

// ---------------- launch ------------------------------------------------------
extern "C" void kernel_launch(void* const* d_in, const int* in_sizes, int n_in,
                              void* d_out, int out_size)
{
    const float* x        = (const float*)d_in[0];
    const float* enc_in_w = (const float*)d_in[1];
    const float* enc_in_b = (const float*)d_in[2];
    const float* qkv_w    = (const float*)d_in[3];
    const float* qkv_b    = (const float*)d_in[4];
    const float* ao_w     = (const float*)d_in[5];
    const float* ao_b     = (const float*)d_in[6];
    const float* ln1_s    = (const float*)d_in[7];
    const float* ln1_b    = (const float*)d_in[8];
    const float* ff1_w    = (const float*)d_in[9];
    const float* ff1_b    = (const float*)d_in[10];
    const float* ff2_w    = (const float*)d_in[11];
    const float* ff2_b    = (const float*)d_in[12];
    const float* ln2_s    = (const float*)d_in[13];
    const float* ln2_b    = (const float*)d_in[14];
    const float* fc_w     = (const float*)d_in[15];
    const float* fc_b     = (const float*)d_in[16];
    const float* lift_w   = (const float*)d_in[17];
    const float* lift_b   = (const float*)d_in[18];
    const float* spec_wr  = (const float*)d_in[19];
    const float* spec_wi  = (const float*)d_in[20];
    const float* skip_w   = (const float*)d_in[21];
    const float* skip_b   = (const float*)d_in[22];
    const float* p1_w     = (const float*)d_in[23];
    const float* p1_b     = (const float*)d_in[24];
    const float* p2_w     = (const float*)d_in[25];
    const float* p2_b     = (const float*)d_in[26];
    float* out = (float*)d_out;

    init_tw_kernel<<<1, 128>>>();
    r_embed<<<1024, 256>>>(x, enc_in_w, enc_in_b);
    for (int l = 0; l < 2; l++) {
        r_qkv   <<<3072, 256>>>(qkv_w + l*HDc*192, qkv_b + l*192);
        r_attn  <<<2048, 256>>>();
        r_ao_ln <<<512, 256>>>(ao_w + l*HDc*HDc, ao_b + l*HDc,
                               ln1_s + l*HDc, ln1_b + l*HDc);
        r_ff1   <<<4096, 256>>>(ff1_w + l*HDc*256, ff1_b + l*256);
        r_ff2_ln<<<512, 256>>>(ff2_w + l*256*HDc, ff2_b + l*HDc,
                               ln2_s + l*HDc, ln2_b + l*HDc);
    }
    r_final<<<Bc, 64>>>(fc_w, fc_b);

    lift_kernel<<<(Bc*Hc*Wcn)/256, 256>>>(x, lift_w, lift_b);

    for (int l = 0; l < NLc; l++) {
        dftw_kernel  <<<Bc*CHc*Hc/32, 128>>>(l);
        dfth_kernel  <<<Bc*CHc, 128>>>();
        spec_kernel  <<<dim3(Bc, 2, 8), 256>>>(spec_wr, spec_wi, l);
        idfth_kernel <<<Bc*CHc, 128>>>();
        combine_kernel<<<Bc*Hc, 128>>>(skip_w, skip_b, l);
    }
    proj_kernel<<<Bc*Hc, 128>>>(out, p1_w, p1_b, p2_w, p2_b);
}